// round 5
// baseline (speedup 1.0000x reference)
#include <cuda_runtime.h>
#include <math.h>
#include <stdint.h>

#define N_NODES 50000
#define E_EDGES 800000
#define E_TOT   (E_EDGES + N_NODES)
#define IN_CH 128
#define H1C 200
#define H2C 100
#define OUTC 2

// ---------------- scratch (static __device__, no allocs) ----------------
__device__ float g_h[(size_t)N_NODES * H1C];
__device__ float g_buf[(size_t)N_NODES * H1C];
__device__ float g_invn[N_NODES];
__device__ int   g_deg[N_NODES];
__device__ int   g_rowptr[N_NODES + 1];
__device__ int   g_cursor[N_NODES];
__device__ int   g_csrsrc[E_TOT];

// ---------------- Threefry-2x32 (matches JAX, confirmed) ----------------
__host__ __device__ inline uint32_t rotl32(uint32_t v, int d) {
    return (v << d) | (v >> (32 - d));
}
__host__ __device__ inline void threefry2x32(uint32_t key0, uint32_t key1,
                                             uint32_t x0, uint32_t x1,
                                             uint32_t& o0, uint32_t& o1) {
    uint32_t ks[3] = {key0, key1, key0 ^ key1 ^ 0x1BD11BDAu};
    const int rot[8] = {13, 15, 26, 6, 17, 29, 16, 24};
    x0 += ks[0]; x1 += ks[1];
#pragma unroll
    for (int i = 0; i < 5; i++) {
        const int* r = &rot[(i & 1) * 4];
#pragma unroll
        for (int j = 0; j < 4; j++) { x0 += x1; x1 = rotl32(x1, r[j]); x1 ^= x0; }
        x0 += ks[(i + 1) % 3];
        x1 += ks[(i + 2) % 3] + (uint32_t)(i + 1);
    }
    o0 = x0; o1 = x1;
}

// ---------------- CSR build ----------------
__global__ void k_init() {
    int i = blockIdx.x * blockDim.x + threadIdx.x;
    if (i < N_NODES) { g_deg[i] = 1; g_cursor[i] = 0; }  // deg=1 => self-loop
}
__global__ void k_count(const int* __restrict__ dst) {
    int e = blockIdx.x * blockDim.x + threadIdx.x;
    if (e < E_EDGES) atomicAdd(&g_deg[dst[e]], 1);
}
__global__ void k_scan() {  // single block, 1024 threads
    __shared__ int sh[1024];
    int tid = threadIdx.x;
    const int CH = (N_NODES + 1023) / 1024;
    int base = tid * CH;
    int s = 0;
    for (int i = 0; i < CH; i++) {
        int idx = base + i;
        if (idx < N_NODES) s += g_deg[idx];
    }
    sh[tid] = s;
    __syncthreads();
    for (int off = 1; off < 1024; off <<= 1) {
        int v = (tid >= off) ? sh[tid - off] : 0;
        __syncthreads();
        sh[tid] += v;
        __syncthreads();
    }
    int run = (tid == 0) ? 0 : sh[tid - 1];
    for (int i = 0; i < CH; i++) {
        int idx = base + i;
        if (idx < N_NODES) { g_rowptr[idx] = run; run += g_deg[idx]; }
    }
    if (tid == 1023) g_rowptr[N_NODES] = sh[1023];
}
__global__ void k_fill(const int* __restrict__ src, const int* __restrict__ dst) {
    int e = blockIdx.x * blockDim.x + threadIdx.x;
    if (e >= E_TOT) return;
    int s, d;
    if (e < E_EDGES) { s = src[e]; d = dst[e]; }
    else             { s = e - E_EDGES; d = s; }
    int pos = atomicAdd(&g_cursor[d], 1);
    g_csrsrc[g_rowptr[d] + pos] = s;
}

// ---------------- 3xTF32 tensor-core GEMM (near-fp32 accuracy) ----------------
// C = A@B; A,B split into tf32 hi+lo; C = Ah*Bh + Ah*Bl + Al*Bh.
#define AS_STRIDE 36
#define BS_STRIDE 72

__device__ __forceinline__ uint32_t f2tf32(float f) {
    uint32_t o;
    asm volatile("cvt.rna.tf32.f32 %0, %1;" : "=r"(o) : "f"(f));
    return o;
}
__device__ __forceinline__ void split_tf32(float f, uint32_t& hi, uint32_t& lo) {
    hi = f2tf32(f);
    lo = f2tf32(f - __uint_as_float(hi));
}
__device__ __forceinline__ void mma_tf32(float* c, const uint32_t* a, const uint32_t* b) {
    asm volatile(
        "mma.sync.aligned.m16n8k8.row.col.f32.tf32.tf32.f32 "
        "{%0,%1,%2,%3}, {%4,%5,%6,%7}, {%8,%9}, {%0,%1,%2,%3};\n"
        : "+f"(c[0]), "+f"(c[1]), "+f"(c[2]), "+f"(c[3])
        : "r"(a[0]), "r"(a[1]), "r"(a[2]), "r"(a[3]), "r"(b[0]), "r"(b[1]));
}

// SRC: 0 = external A param, 1 = g_buf. Output always g_h.
template <int SRC>
__global__ void __launch_bounds__(256) gemm_tf32x3(const float* __restrict__ Aext,
                                                   const float* __restrict__ B,
                                                   int M, int N, int K) {
    const float* A = (SRC == 0) ? Aext : g_buf;
    __shared__ uint32_t AsH[128 * AS_STRIDE];
    __shared__ uint32_t AsL[128 * AS_STRIDE];
    __shared__ uint32_t BsH[32 * BS_STRIDE];
    __shared__ uint32_t BsL[32 * BS_STRIDE];
    const int tid = threadIdx.x;
    const int wid = tid >> 5, lane = tid & 31;
    const int g = lane >> 2, t = lane & 3;
    const int warpM = wid >> 1, warpN = wid & 1;
    const int rowBase = blockIdx.y * 128, colBase = blockIdx.x * 64;

    float acc[2][4][4];
#pragma unroll
    for (int mt = 0; mt < 2; mt++)
#pragma unroll
        for (int nt = 0; nt < 4; nt++)
#pragma unroll
            for (int r = 0; r < 4; r++) acc[mt][nt][r] = 0.f;

    const int nCh = (K + 31) / 32;
    for (int ch = 0; ch < nCh; ch++) {
        const int k0 = ch * 32;
        // ---- A tile 128x32 ----
#pragma unroll
        for (int i = 0; i < 4; i++) {
            int f = tid + i * 256;
            int r = f >> 3, c4 = f & 7;
            int gr = rowBase + r, gk = k0 + c4 * 4;
            float4 v = make_float4(0.f, 0.f, 0.f, 0.f);
            if (gr < M && gk < K)
                v = *reinterpret_cast<const float4*>(A + (size_t)gr * K + gk);
            uint4 uh, ul;
            split_tf32(v.x, uh.x, ul.x); split_tf32(v.y, uh.y, ul.y);
            split_tf32(v.z, uh.z, ul.z); split_tf32(v.w, uh.w, ul.w);
            *reinterpret_cast<uint4*>(&AsH[r * AS_STRIDE + c4 * 4]) = uh;
            *reinterpret_cast<uint4*>(&AsL[r * AS_STRIDE + c4 * 4]) = ul;
        }
        // ---- B tile 32x64 ----
#pragma unroll
        for (int i = 0; i < 2; i++) {
            int f = tid + i * 256;
            int r = f >> 4, c4 = f & 15;
            int gk = k0 + r, gn = colBase + c4 * 4;
            float4 v = make_float4(0.f, 0.f, 0.f, 0.f);
            if (gk < K && gn < N)
                v = *reinterpret_cast<const float4*>(B + (size_t)gk * N + gn);
            uint4 uh, ul;
            split_tf32(v.x, uh.x, ul.x); split_tf32(v.y, uh.y, ul.y);
            split_tf32(v.z, uh.z, ul.z); split_tf32(v.w, uh.w, ul.w);
            *reinterpret_cast<uint4*>(&BsH[r * BS_STRIDE + c4 * 4]) = uh;
            *reinterpret_cast<uint4*>(&BsL[r * BS_STRIDE + c4 * 4]) = ul;
        }
        __syncthreads();
#pragma unroll
        for (int kk = 0; kk < 4; kk++) {
            const int kl = kk * 8;
            uint32_t afH[2][4], afL[2][4];
#pragma unroll
            for (int mt = 0; mt < 2; mt++) {
                int m0 = warpM * 32 + mt * 16 + g;
                afH[mt][0] = AsH[m0 * AS_STRIDE + kl + t];
                afH[mt][1] = AsH[(m0 + 8) * AS_STRIDE + kl + t];
                afH[mt][2] = AsH[m0 * AS_STRIDE + kl + t + 4];
                afH[mt][3] = AsH[(m0 + 8) * AS_STRIDE + kl + t + 4];
                afL[mt][0] = AsL[m0 * AS_STRIDE + kl + t];
                afL[mt][1] = AsL[(m0 + 8) * AS_STRIDE + kl + t];
                afL[mt][2] = AsL[m0 * AS_STRIDE + kl + t + 4];
                afL[mt][3] = AsL[(m0 + 8) * AS_STRIDE + kl + t + 4];
            }
#pragma unroll
            for (int nt = 0; nt < 4; nt++) {
                int n0 = warpN * 32 + nt * 8 + g;
                uint32_t bfH[2], bfL[2];
                bfH[0] = BsH[(kl + t) * BS_STRIDE + n0];
                bfH[1] = BsH[(kl + t + 4) * BS_STRIDE + n0];
                bfL[0] = BsL[(kl + t) * BS_STRIDE + n0];
                bfL[1] = BsL[(kl + t + 4) * BS_STRIDE + n0];
#pragma unroll
                for (int mt = 0; mt < 2; mt++) {
                    mma_tf32(acc[mt][nt], afH[mt], bfL);   // hi*lo
                    mma_tf32(acc[mt][nt], afL[mt], bfH);   // lo*hi
                    mma_tf32(acc[mt][nt], afH[mt], bfH);   // hi*hi
                }
            }
        }
        __syncthreads();
    }
#pragma unroll
    for (int mt = 0; mt < 2; mt++) {
#pragma unroll
        for (int nt = 0; nt < 4; nt++) {
            int n = colBase + warpN * 32 + nt * 8 + t * 2;
            if (n >= N) continue;
#pragma unroll
            for (int half = 0; half < 2; half++) {
                int m = rowBase + warpM * 32 + mt * 16 + g + half * 8;
                if (m < M) {
                    float2 o = make_float2(acc[mt][nt][half * 2], acc[mt][nt][half * 2 + 1]);
                    *reinterpret_cast<float2*>(g_h + (size_t)m * N + n) = o;
                }
            }
        }
    }
}

// ---------------- row inverse-norm (reads g_h) ----------------
template <int D>
__global__ void k_norm() {
    int gw = (blockIdx.x * blockDim.x + threadIdx.x) >> 5;
    int lane = threadIdx.x & 31;
    if (gw >= N_NODES) return;
    float s = 0.0f;
    for (int d = lane; d < D; d += 32) {
        float v = g_h[(size_t)gw * D + d];
        s += v * v;
    }
#pragma unroll
    for (int o = 16; o; o >>= 1) s += __shfl_xor_sync(0xffffffffu, s, o);
    if (lane == 0) g_invn[gw] = 1.0f / fmaxf(sqrtf(s), 1e-12f);
}

// ---------------- fused attention + softmax + agg + relu + dropout ----------
// One warp per dst node. Logits = beta*cosine are in [-|beta|,|beta|]: no max
// subtraction needed (exp cannot overflow). Each edge independent -> unroll 2.
template <int D, bool DROP>
__global__ void k_node(const float* __restrict__ beta_p, uint32_t key0, uint32_t key1) {
    int v = (blockIdx.x * blockDim.x + threadIdx.x) >> 5;
    int lane = threadIdx.x & 31;
    if (v >= N_NODES) return;
    const float* h = g_h;
    constexpr int R = (D + 31) / 32;
    float hv[R];
#pragma unroll
    for (int j = 0; j < R; j++) {
        int d = lane + 32 * j;
        hv[j] = (d < D) ? h[(size_t)v * D + d] : 0.0f;
    }
    float bi = __ldg(beta_p) * g_invn[v];
    int e0 = g_rowptr[v], e1 = g_rowptr[v + 1];
    float denom = 0.0f;
    float acc[R];
#pragma unroll
    for (int j = 0; j < R; j++) acc[j] = 0.0f;

    for (int e = e0; e < e1; e += 2) {
        bool hasB = (e + 1 < e1);
        int sA = g_csrsrc[e];
        int sB = hasB ? g_csrsrc[e + 1] : sA;
        float invA = g_invn[sA], invB = g_invn[sB];
        float hsA[R], hsB[R];
#pragma unroll
        for (int j = 0; j < R; j++) {
            int d = lane + 32 * j;
            hsA[j] = (d < D) ? h[(size_t)sA * D + d] : 0.0f;
            hsB[j] = (d < D) ? h[(size_t)sB * D + d] : 0.0f;
        }
        float dA = 0.f, dB = 0.f;
#pragma unroll
        for (int j = 0; j < R; j++) { dA += hv[j] * hsA[j]; dB += hv[j] * hsB[j]; }
#pragma unroll
        for (int o = 16; o; o >>= 1) {
            dA += __shfl_xor_sync(0xffffffffu, dA, o);
            dB += __shfl_xor_sync(0xffffffffu, dB, o);
        }
        float wA = __expf(bi * dA * invA);
        float wB = hasB ? __expf(bi * dB * invB) : 0.0f;
        denom += wA + wB;
#pragma unroll
        for (int j = 0; j < R; j++) acc[j] += wA * hsA[j] + wB * hsB[j];
    }
    float dinv = 1.0f / fmaxf(denom, 1e-12f);
#pragma unroll
    for (int j = 0; j < R; j++) {
        int d = lane + 32 * j;
        if (d >= D) continue;
        float val = fmaxf(acc[j] * dinv, 0.0f);
        if (DROP) {
            uint32_t idx = (uint32_t)v * (uint32_t)D + (uint32_t)d;
            uint32_t b0, b1;
            threefry2x32(key0, key1, 0u, idx, b0, b1);
            uint32_t bits = b0 ^ b1;
            float u = __uint_as_float((bits >> 9) | 0x3f800000u) - 1.0f;
            val = (u < 0.9f) ? (val / 0.9f) : 0.0f;
        }
        g_buf[(size_t)v * D + d] = val;
    }
}

// ---------------- layer 3 dedicated path (D=2) ----------------
__global__ void k_gemm3_norm(const float* __restrict__ W3) {
    int v = (blockIdx.x * blockDim.x + threadIdx.x) >> 5;
    int lane = threadIdx.x & 31;
    if (v >= N_NODES) return;
    float s0 = 0.f, s1 = 0.f;
#pragma unroll
    for (int j = 0; j < 4; j++) {
        int d = lane + 32 * j;
        if (d < H2C) {
            float hval = g_buf[(size_t)v * H2C + d];
            s0 += hval * __ldg(W3 + d * 2 + 0);
            s1 += hval * __ldg(W3 + d * 2 + 1);
        }
    }
#pragma unroll
    for (int o = 16; o; o >>= 1) {
        s0 += __shfl_xor_sync(0xffffffffu, s0, o);
        s1 += __shfl_xor_sync(0xffffffffu, s1, o);
    }
    if (lane == 0) {
        g_h[(size_t)v * 2 + 0] = s0;
        g_h[(size_t)v * 2 + 1] = s1;
        g_invn[v] = 1.0f / fmaxf(sqrtf(s0 * s0 + s1 * s1), 1e-12f);
    }
}

__global__ void k_node3(const float* __restrict__ beta_p, float* __restrict__ out) {
    int v = blockIdx.x * blockDim.x + threadIdx.x;
    if (v >= N_NODES) return;
    const float2* h2 = reinterpret_cast<const float2*>(g_h);
    float2 hv = h2[v];
    float bi = __ldg(beta_p) * g_invn[v];
    int e0 = g_rowptr[v], e1 = g_rowptr[v + 1];
    float denom = 0.f, a0 = 0.f, a1 = 0.f;
    for (int e = e0; e < e1; e++) {
        int s = g_csrsrc[e];
        float2 hs = h2[s];
        float w = __expf(bi * (hv.x * hs.x + hv.y * hs.y) * g_invn[s]);
        denom += w;
        a0 += w * hs.x;
        a1 += w * hs.y;
    }
    float dinv = 1.0f / fmaxf(denom, 1e-12f);
    out[(size_t)v * 2 + 0] = fmaxf(a0 * dinv, 0.f);
    out[(size_t)v * 2 + 1] = fmaxf(a1 * dinv, 0.f);
}

extern "C" void kernel_launch(void* const* d_in, const int* in_sizes, int n_in,
                              void* d_out, int out_size) {
    const float* x  = (const float*)d_in[0];
    const int*   ei = (const int*)d_in[1];
    const float* W1 = (const float*)d_in[2];
    const float* W2 = (const float*)d_in[3];
    const float* W3 = (const float*)d_in[4];
    const float* b1 = (const float*)d_in[5];
    const float* b2 = (const float*)d_in[6];
    const float* b3 = (const float*)d_in[7];
    float* out = (float*)d_out;
    const int* src = ei;
    const int* dst = ei + E_EDGES;

    uint32_t k1a, k1b, k2a, k2b;
    threefry2x32(0u, 42u, 0u, 0u, k1a, k1b);
    threefry2x32(0u, 42u, 0u, 1u, k2a, k2b);

    // ---- CSR build (includes self-loops) ----
    k_init<<<(N_NODES + 255) / 256, 256>>>();
    k_count<<<(E_EDGES + 255) / 256, 256>>>(dst);
    k_scan<<<1, 1024>>>();
    k_fill<<<(E_TOT + 255) / 256, 256>>>(src, dst);

    const int warpGrid = (N_NODES * 32 + 255) / 256;

    // ---- layer 1: 128 -> 200 ----
    {
        dim3 g((H1C + 63) / 64, (N_NODES + 127) / 128);
        gemm_tf32x3<0><<<g, 256>>>(x, W1, N_NODES, H1C, IN_CH);
        k_norm<H1C><<<warpGrid, 256>>>();
        k_node<H1C, true><<<warpGrid, 256>>>(b1, k1a, k1b);
    }
    // ---- layer 2: 200 -> 100 ----
    {
        dim3 g((H2C + 63) / 64, (N_NODES + 127) / 128);
        gemm_tf32x3<1><<<g, 256>>>(nullptr, W2, N_NODES, H2C, H1C);
        k_norm<H2C><<<warpGrid, 256>>>();
        k_node<H2C, true><<<warpGrid, 256>>>(b2, k2a, k2b);
    }
    // ---- layer 3: 100 -> 2 (no dropout), dedicated path ----
    {
        k_gemm3_norm<<<warpGrid, 256>>>(W3);
        k_node3<<<(N_NODES + 255) / 256, 256>>>(b3, out);
    }
    (void)in_sizes; (void)n_in; (void)out_size;
}

// round 6
// speedup vs baseline: 1.1666x; 1.1666x over previous
#include <cuda_runtime.h>
#include <math.h>
#include <stdint.h>

#define N_NODES 50000
#define E_EDGES 800000
#define E_TOT   (E_EDGES + N_NODES)
#define IN_CH 128
#define H1C 200
#define H2C 100
#define OUTC 2

#define GEMM1_NCT    4                     // ceil(200/64)
#define GEMM1_NRT    391                   // ceil(50000/128)
#define GEMM1_BLOCKS (GEMM1_NCT * GEMM1_NRT)
#define COUNT_BLOCKS 3125                  // ceil(800000/256)
#define GEMM2_NCT    2                     // ceil(100/64)
#define GEMM2_BLOCKS (GEMM2_NCT * GEMM1_NRT)
#define FILL_BLOCKS  3321                  // ceil(850000/256)
#define NORM_BLOCKS  6250                  // 50000 warps / 8
#define SCAN_BLOCKS  196                   // ceil(50000/256)

// ---------------- scratch (static __device__, no allocs) ----------------
__device__ float g_h[(size_t)N_NODES * H1C];
__device__ float g_buf[(size_t)N_NODES * H1C];
__device__ float g_invn[N_NODES];
__device__ int   g_deg[N_NODES];
__device__ int   g_rowptr[N_NODES + 1];
__device__ int   g_cursor[N_NODES];
__device__ int   g_csrsrc[E_TOT];
__device__ int   g_bsum[256];

// ---------------- Threefry-2x32 (matches JAX, confirmed) ----------------
__host__ __device__ inline uint32_t rotl32(uint32_t v, int d) {
    return (v << d) | (v >> (32 - d));
}
__host__ __device__ inline void threefry2x32(uint32_t key0, uint32_t key1,
                                             uint32_t x0, uint32_t x1,
                                             uint32_t& o0, uint32_t& o1) {
    uint32_t ks[3] = {key0, key1, key0 ^ key1 ^ 0x1BD11BDAu};
    const int rot[8] = {13, 15, 26, 6, 17, 29, 16, 24};
    x0 += ks[0]; x1 += ks[1];
#pragma unroll
    for (int i = 0; i < 5; i++) {
        const int* r = &rot[(i & 1) * 4];
#pragma unroll
        for (int j = 0; j < 4; j++) { x0 += x1; x1 = rotl32(x1, r[j]); x1 ^= x0; }
        x0 += ks[(i + 1) % 3];
        x1 += ks[(i + 2) % 3] + (uint32_t)(i + 1);
    }
    o0 = x0; o1 = x1;
}

// ---------------- cp.async helpers ----------------
__device__ __forceinline__ void cp_async16(void* smem_dst, const void* gsrc, bool valid) {
    uint32_t saddr = (uint32_t)__cvta_generic_to_shared(smem_dst);
    int bytes = valid ? 16 : 0;
    asm volatile("cp.async.cg.shared.global [%0], [%1], 16, %2;\n"
                 :: "r"(saddr), "l"(gsrc), "r"(bytes));
}
#define CP_COMMIT()  asm volatile("cp.async.commit_group;\n")
#define CP_WAIT(n)   asm volatile("cp.async.wait_group %0;\n" :: "n"(n))

// ---------------- tf32 helpers ----------------
__device__ __forceinline__ uint32_t f2tf32(float f) {
    uint32_t o;
    asm volatile("cvt.rna.tf32.f32 %0, %1;" : "=r"(o) : "f"(f));
    return o;
}
__device__ __forceinline__ void split_tf32(float f, uint32_t& hi, uint32_t& lo) {
    hi = f2tf32(f);
    lo = f2tf32(f - __uint_as_float(hi));
}
__device__ __forceinline__ void mma_tf32(float* c, const uint32_t* a, const uint32_t* b) {
    asm volatile(
        "mma.sync.aligned.m16n8k8.row.col.f32.tf32.tf32.f32 "
        "{%0,%1,%2,%3}, {%4,%5,%6,%7}, {%8,%9}, {%0,%1,%2,%3};\n"
        : "+f"(c[0]), "+f"(c[1]), "+f"(c[2]), "+f"(c[3])
        : "r"(a[0]), "r"(a[1]), "r"(a[2]), "r"(a[3]), "r"(b[0]), "r"(b[1]));
}

// ---------------- 3xTF32 GEMM body: cp.async double-buffered ----------------
// Block tile 128x64x32, 8 warps (4m x 2n), warp tile 32x32 (2x4 m16n8 tiles).
// Raw fp32 staged in smem; hi/lo split at fragment load. Output -> g_h.
#define AST 36
#define BST 72
template <int SRC>
__device__ __forceinline__ void gemm_body(const float* __restrict__ Aext,
                                          const float* __restrict__ B,
                                          int M, int N, int K,
                                          int bx, int nColTiles) {
    const float* A = (SRC == 0) ? Aext : g_buf;
    __shared__ __align__(16) float AsF[2][128 * AST];
    __shared__ __align__(16) float BsF[2][32 * BST];
    const int tid = threadIdx.x;
    const int wid = tid >> 5, lane = tid & 31;
    const int g = lane >> 2, t = lane & 3;
    const int warpM = wid >> 1, warpN = wid & 1;
    const int rowBase = (bx / nColTiles) * 128, colBase = (bx % nColTiles) * 64;

    auto issue = [&](int ch, int buf) {
        const int k0 = ch * 32;
#pragma unroll
        for (int i = 0; i < 4; i++) {
            int f = tid + i * 256;
            int r = f >> 3, c4 = f & 7;
            int gr = rowBase + r, gk = k0 + c4 * 4;
            bool ok = (gr < M) && (gk < K);       // K%4==0, so 16B all-or-nothing
            const float* src = ok ? (A + (size_t)gr * K + gk) : A;
            cp_async16(&AsF[buf][r * AST + c4 * 4], src, ok);
        }
#pragma unroll
        for (int i = 0; i < 2; i++) {
            int f = tid + i * 256;
            int r = f >> 4, c4 = f & 15;
            int gk = k0 + r, gn = colBase + c4 * 4;
            bool ok = (gk < K) && (gn < N);       // N%4==0
            const float* src = ok ? (B + (size_t)gk * N + gn) : B;
            cp_async16(&BsF[buf][r * BST + c4 * 4], src, ok);
        }
        CP_COMMIT();
    };

    float acc[2][4][4];
#pragma unroll
    for (int mt = 0; mt < 2; mt++)
#pragma unroll
        for (int nt = 0; nt < 4; nt++)
#pragma unroll
            for (int r = 0; r < 4; r++) acc[mt][nt][r] = 0.f;

    const int nCh = (K + 31) / 32;
    issue(0, 0);
    for (int ch = 0; ch < nCh; ch++) {
        const int cur = ch & 1;
        if (ch + 1 < nCh) { issue(ch + 1, cur ^ 1); CP_WAIT(1); }
        else              { CP_WAIT(0); }
        __syncthreads();
#pragma unroll
        for (int kk = 0; kk < 4; kk++) {
            const int kl = kk * 8;
            uint32_t aH[2][4], aL[2][4];
#pragma unroll
            for (int mt = 0; mt < 2; mt++) {
                int m0 = warpM * 32 + mt * 16 + g;
                float a0 = AsF[cur][m0 * AST + kl + t];
                float a1 = AsF[cur][(m0 + 8) * AST + kl + t];
                float a2 = AsF[cur][m0 * AST + kl + t + 4];
                float a3 = AsF[cur][(m0 + 8) * AST + kl + t + 4];
                split_tf32(a0, aH[mt][0], aL[mt][0]);
                split_tf32(a1, aH[mt][1], aL[mt][1]);
                split_tf32(a2, aH[mt][2], aL[mt][2]);
                split_tf32(a3, aH[mt][3], aL[mt][3]);
            }
#pragma unroll
            for (int nt = 0; nt < 4; nt++) {
                int n0 = warpN * 32 + nt * 8 + g;
                float b0 = BsF[cur][(kl + t) * BST + n0];
                float b1 = BsF[cur][(kl + t + 4) * BST + n0];
                uint32_t bH[2], bL[2];
                split_tf32(b0, bH[0], bL[0]);
                split_tf32(b1, bH[1], bL[1]);
#pragma unroll
                for (int mt = 0; mt < 2; mt++) {
                    mma_tf32(acc[mt][nt], aH[mt], bL);
                    mma_tf32(acc[mt][nt], aL[mt], bH);
                    mma_tf32(acc[mt][nt], aH[mt], bH);
                }
            }
        }
        __syncthreads();
    }
#pragma unroll
    for (int mt = 0; mt < 2; mt++) {
#pragma unroll
        for (int nt = 0; nt < 4; nt++) {
            int n = colBase + warpN * 32 + nt * 8 + t * 2;
            if (n >= N) continue;
#pragma unroll
            for (int half = 0; half < 2; half++) {
                int m = rowBase + warpM * 32 + mt * 16 + g + half * 8;
                if (m < M) {
                    float2 o = make_float2(acc[mt][nt][half * 2], acc[mt][nt][half * 2 + 1]);
                    *reinterpret_cast<float2*>(g_h + (size_t)m * N + n) = o;
                }
            }
        }
    }
}

// ---------------- norm body ----------------
template <int D>
__device__ __forceinline__ void norm_body(int gw, int lane) {
    if (gw >= N_NODES) return;
    float s = 0.0f;
    for (int d = lane; d < D; d += 32) {
        float v = g_h[(size_t)gw * D + d];
        s += v * v;
    }
#pragma unroll
    for (int o = 16; o; o >>= 1) s += __shfl_xor_sync(0xffffffffu, s, o);
    if (lane == 0) g_invn[gw] = 1.0f / fmaxf(sqrtf(s), 1e-12f);
}

// ---------------- kernels ----------------
__global__ void k_init() {
    int i = blockIdx.x * blockDim.x + threadIdx.x;
    if (i < N_NODES) { g_deg[i] = 1; g_cursor[i] = 0; }  // deg=1 => self-loop
}

// fused: [GEMM1 | edge count]
__global__ void __launch_bounds__(256) k_gemm1_count(const float* __restrict__ x,
                                                     const float* __restrict__ W1,
                                                     const int* __restrict__ dst) {
    if (blockIdx.x < GEMM1_BLOCKS) {
        gemm_body<0>(x, W1, N_NODES, H1C, IN_CH, blockIdx.x, GEMM1_NCT);
    } else {
        int e = (blockIdx.x - GEMM1_BLOCKS) * 256 + threadIdx.x;
        if (e < E_EDGES) atomicAdd(&g_deg[dst[e]], 1);
    }
}

__global__ void k_scan1() {
    __shared__ int sh[256];
    int b = blockIdx.x, t = threadIdx.x, i = b * 256 + t;
    int v = (i < N_NODES) ? g_deg[i] : 0;
    sh[t] = v;
    __syncthreads();
    for (int off = 1; off < 256; off <<= 1) {
        int x = (t >= off) ? sh[t - off] : 0;
        __syncthreads();
        sh[t] += x;
        __syncthreads();
    }
    if (i < N_NODES) g_rowptr[i] = sh[t] - v;  // local exclusive prefix
    if (t == 255) g_bsum[b] = sh[255];
}
__global__ void k_scan2() {
    __shared__ int sh[256];
    int t = threadIdx.x;
    int v = (t < SCAN_BLOCKS) ? g_bsum[t] : 0;
    sh[t] = v;
    __syncthreads();
    for (int off = 1; off < 256; off <<= 1) {
        int x = (t >= off) ? sh[t - off] : 0;
        __syncthreads();
        sh[t] += x;
        __syncthreads();
    }
    g_bsum[t] = sh[t] - v;  // exclusive block offsets
}
__global__ void k_scan3() {
    int i = blockIdx.x * blockDim.x + threadIdx.x;
    if (i < N_NODES) g_rowptr[i] += g_bsum[i >> 8];
    if (i == 0) g_rowptr[N_NODES] = E_TOT;
}

// fused: [CSR fill | norm layer1]
__global__ void k_fill_norm1(const int* __restrict__ src, const int* __restrict__ dst) {
    if (blockIdx.x < FILL_BLOCKS) {
        int e = blockIdx.x * 256 + threadIdx.x;
        if (e >= E_TOT) return;
        int s, d;
        if (e < E_EDGES) { s = src[e]; d = dst[e]; }
        else             { s = e - E_EDGES; d = s; }
        int pos = atomicAdd(&g_cursor[d], 1);
        g_csrsrc[g_rowptr[d] + pos] = s;
    } else {
        int gw = ((blockIdx.x - FILL_BLOCKS) * 256 + threadIdx.x) >> 5;
        norm_body<H1C>(gw, threadIdx.x & 31);
    }
}

__global__ void __launch_bounds__(256) k_gemm2(const float* __restrict__ W2) {
    gemm_body<1>(nullptr, W2, N_NODES, H2C, H1C, blockIdx.x, GEMM2_NCT);
}

template <int D>
__global__ void k_norm() {
    norm_body<D>((blockIdx.x * blockDim.x + threadIdx.x) >> 5, threadIdx.x & 31);
}

// ---------------- fused attention + softmax + agg + relu + dropout ----------
// One warp per dst node. Logits in [-|beta|,|beta|]: no max subtraction needed.
template <int D, bool DROP>
__global__ void k_node(const float* __restrict__ beta_p, uint32_t key0, uint32_t key1) {
    int v = (blockIdx.x * blockDim.x + threadIdx.x) >> 5;
    int lane = threadIdx.x & 31;
    if (v >= N_NODES) return;
    const float* h = g_h;
    constexpr int R = (D + 31) / 32;
    float hv[R];
#pragma unroll
    for (int j = 0; j < R; j++) {
        int d = lane + 32 * j;
        hv[j] = (d < D) ? h[(size_t)v * D + d] : 0.0f;
    }
    float bi = __ldg(beta_p) * g_invn[v];
    int e0 = g_rowptr[v], e1 = g_rowptr[v + 1];
    float denom = 0.0f;
    float acc[R];
#pragma unroll
    for (int j = 0; j < R; j++) acc[j] = 0.0f;

    for (int e = e0; e < e1; e += 2) {
        bool hasB = (e + 1 < e1);
        int sA = g_csrsrc[e];
        int sB = hasB ? g_csrsrc[e + 1] : sA;
        float invA = g_invn[sA], invB = g_invn[sB];
        float hsA[R], hsB[R];
#pragma unroll
        for (int j = 0; j < R; j++) {
            int d = lane + 32 * j;
            hsA[j] = (d < D) ? h[(size_t)sA * D + d] : 0.0f;
            hsB[j] = (d < D) ? h[(size_t)sB * D + d] : 0.0f;
        }
        float dA = 0.f, dB = 0.f;
#pragma unroll
        for (int j = 0; j < R; j++) { dA += hv[j] * hsA[j]; dB += hv[j] * hsB[j]; }
#pragma unroll
        for (int o = 16; o; o >>= 1) {
            dA += __shfl_xor_sync(0xffffffffu, dA, o);
            dB += __shfl_xor_sync(0xffffffffu, dB, o);
        }
        float wA = __expf(bi * dA * invA);
        float wB = hasB ? __expf(bi * dB * invB) : 0.0f;
        denom += wA + wB;
#pragma unroll
        for (int j = 0; j < R; j++) acc[j] += wA * hsA[j] + wB * hsB[j];
    }
    float dinv = 1.0f / fmaxf(denom, 1e-12f);
#pragma unroll
    for (int j = 0; j < R; j++) {
        int d = lane + 32 * j;
        if (d >= D) continue;
        float val = fmaxf(acc[j] * dinv, 0.0f);
        if (DROP) {
            uint32_t idx = (uint32_t)v * (uint32_t)D + (uint32_t)d;
            uint32_t b0, b1;
            threefry2x32(key0, key1, 0u, idx, b0, b1);
            uint32_t bits = b0 ^ b1;
            float u = __uint_as_float((bits >> 9) | 0x3f800000u) - 1.0f;
            val = (u < 0.9f) ? (val / 0.9f) : 0.0f;
        }
        g_buf[(size_t)v * D + d] = val;
    }
}

// ---------------- layer 3 dedicated path (D=2) ----------------
__global__ void k_gemm3_norm(const float* __restrict__ W3) {
    int v = (blockIdx.x * blockDim.x + threadIdx.x) >> 5;
    int lane = threadIdx.x & 31;
    if (v >= N_NODES) return;
    float s0 = 0.f, s1 = 0.f;
#pragma unroll
    for (int j = 0; j < 4; j++) {
        int d = lane + 32 * j;
        if (d < H2C) {
            float hval = g_buf[(size_t)v * H2C + d];
            s0 += hval * __ldg(W3 + d * 2 + 0);
            s1 += hval * __ldg(W3 + d * 2 + 1);
        }
    }
#pragma unroll
    for (int o = 16; o; o >>= 1) {
        s0 += __shfl_xor_sync(0xffffffffu, s0, o);
        s1 += __shfl_xor_sync(0xffffffffu, s1, o);
    }
    if (lane == 0) {
        g_h[(size_t)v * 2 + 0] = s0;
        g_h[(size_t)v * 2 + 1] = s1;
        g_invn[v] = 1.0f / fmaxf(sqrtf(s0 * s0 + s1 * s1), 1e-12f);
    }
}

__global__ void k_node3(const float* __restrict__ beta_p, float* __restrict__ out) {
    int v = blockIdx.x * blockDim.x + threadIdx.x;
    if (v >= N_NODES) return;
    const float2* h2 = reinterpret_cast<const float2*>(g_h);
    float2 hv = h2[v];
    float bi = __ldg(beta_p) * g_invn[v];
    int e0 = g_rowptr[v], e1 = g_rowptr[v + 1];
    float denom = 0.f, a0 = 0.f, a1 = 0.f;
    for (int e = e0; e < e1; e++) {
        int s = g_csrsrc[e];
        float2 hs = h2[s];
        float w = __expf(bi * (hv.x * hs.x + hv.y * hs.y) * g_invn[s]);
        denom += w;
        a0 += w * hs.x;
        a1 += w * hs.y;
    }
    float dinv = 1.0f / fmaxf(denom, 1e-12f);
    out[(size_t)v * 2 + 0] = fmaxf(a0 * dinv, 0.f);
    out[(size_t)v * 2 + 1] = fmaxf(a1 * dinv, 0.f);
}

extern "C" void kernel_launch(void* const* d_in, const int* in_sizes, int n_in,
                              void* d_out, int out_size) {
    const float* x  = (const float*)d_in[0];
    const int*   ei = (const int*)d_in[1];
    const float* W1 = (const float*)d_in[2];
    const float* W2 = (const float*)d_in[3];
    const float* W3 = (const float*)d_in[4];
    const float* b1 = (const float*)d_in[5];
    const float* b2 = (const float*)d_in[6];
    const float* b3 = (const float*)d_in[7];
    float* out = (float*)d_out;
    const int* src = ei;
    const int* dst = ei + E_EDGES;

    uint32_t k1a, k1b, k2a, k2b;
    threefry2x32(0u, 42u, 0u, 0u, k1a, k1b);
    threefry2x32(0u, 42u, 0u, 1u, k2a, k2b);

    k_init<<<SCAN_BLOCKS, 256>>>();
    k_gemm1_count<<<GEMM1_BLOCKS + COUNT_BLOCKS, 256>>>(x, W1, dst);
    k_scan1<<<SCAN_BLOCKS, 256>>>();
    k_scan2<<<1, 256>>>();
    k_scan3<<<SCAN_BLOCKS, 256>>>();
    k_fill_norm1<<<FILL_BLOCKS + NORM_BLOCKS, 256>>>(src, dst);
    k_node<H1C, true><<<NORM_BLOCKS, 256>>>(b1, k1a, k1b);
    k_gemm2<<<GEMM2_BLOCKS, 256>>>(W2);
    k_norm<H2C><<<NORM_BLOCKS, 256>>>();
    k_node<H2C, true><<<NORM_BLOCKS, 256>>>(b2, k2a, k2b);
    k_gemm3_norm<<<NORM_BLOCKS, 256>>>(W3);
    k_node3<<<SCAN_BLOCKS, 256>>>(b3, out);
    (void)in_sizes; (void)n_in; (void)out_size;
}